// round 17
// baseline (speedup 1.0000x reference)
#include <cuda_runtime.h>
#include <cstdint>

// Problem constants: D=64, K=1024, N=65536.
#define DIM   64
#define RPT   256        // rows per CTA (1 per thread)
#define CAP   16         // candidate buffer entries per row
#define KMAX  1024

__device__ float g_c2[KMAX];       // ||w_k||^2, exact sequential fp32 chain
__device__ float g_stat[2];        // [0]=swmax (global max|W|), [1]=max_k l1w
__device__ int   g_wq[KMAX * 16];  // packed int8 codebook (4 per int32)

__device__ __forceinline__ int dp4a(int a, int b, int c) {
    int d;
    asm("dp4a.s32.s32 %0, %1, %2, %3;" : "=r"(d) : "r"(a), "r"(b), "r"(c));
    return d;
}

// ---------------------------------------------------------------------------
// prep: one CTA, 256 threads, 4 codes per thread (streaming — no big register
// arrays). Exact c2 chain, global stats, then W int8 quantization with the
// global scale (deterministic rn; re-reads W from L2).
// ---------------------------------------------------------------------------
__global__ void __launch_bounds__(256)
prep_kernel(const float* __restrict__ W, int K) {
    __shared__ float sm[256], sl[256];
    const int tid = threadIdx.x;
    float mx = 0.f, l1m = 0.f;
#pragma unroll
    for (int kk = 0; kk < 4; ++kk) {
        const int k = tid + kk * 256;
        if (k >= K) break;
        const float* w = W + (size_t)k * DIM;
        float c2 = 0.f, l1 = 0.f, m = 0.f;
#pragma unroll
        for (int d = 0; d < DIM; ++d) {
            float v = w[d];
            c2 = __fadd_rn(c2, __fmul_rn(v, v));
            float a = fabsf(v);
            l1 += a;
            m = fmaxf(m, a);
        }
        g_c2[k] = c2;
        mx = fmaxf(mx, m);
        l1m = fmaxf(l1m, l1 * 1.0001f + 1e-12f);
    }
    sm[tid] = mx; sl[tid] = l1m;
    __syncthreads();
    for (int s = 128; s > 0; s >>= 1) {
        if (tid < s) { sm[tid] = fmaxf(sm[tid], sm[tid + s]); sl[tid] = fmaxf(sl[tid], sl[tid + s]); }
        __syncthreads();
    }
    if (tid == 0) { g_stat[0] = fmaxf(sm[0], 1e-30f); g_stat[1] = sl[0]; }
    __syncthreads();
    const float s127 = 127.f / fmaxf(sm[0], 1e-30f);
#pragma unroll
    for (int kk = 0; kk < 4; ++kk) {
        const int k = tid + kk * 256;
        if (k >= K) break;
        const float* w = W + (size_t)k * DIM;
#pragma unroll
        for (int i = 0; i < 16; ++i) {
            int p = 0;
#pragma unroll
            for (int b = 0; b < 4; ++b) {
                int q = __float2int_rn(w[i * 4 + b] * s127);
                q = max(-127, min(127, q));
                p |= (q & 0xff) << (8 * b);
            }
            g_wq[k * 16 + i] = p;
        }
    }
}

// ---------------------------------------------------------------------------
// Main kernel: whole int8 codebook + c2 resident in smem (staged once, no
// syncs in the scan). dp4a filter with cached threshold; rare exact fp32
// rescore reads x and w from GLOBAL (bitwise-identical values -> chain
// identical to reference). One row per thread, ascending scan, strict < and
// ordered deferred rescores -> bit-identical first-index argmin.
// ---------------------------------------------------------------------------
__global__ void __launch_bounds__(256, 2)
vq_main(const float* __restrict__ X, const float* __restrict__ W,
        float* __restrict__ outQ, float* __restrict__ outI, int K)
{
    extern __shared__ char smem[];
    int*   wqs = (int*)smem;                            // [K][16] int   65536 B
    float* c2s = (float*)(smem + KMAX * 64);            // [K]            4096 B
    unsigned short* buf =
        (unsigned short*)(smem + KMAX * 64 + KMAX * 4); // [256][CAP]     8192 B

    const int tid = threadIdx.x;
    const int row = blockIdx.x * RPT + tid;

    // ---- stage whole int8 codebook + c2 into smem (once) ----
    {
        const int4* qsrc = (const int4*)g_wq;
        int4* qdst = (int4*)wqs;
#pragma unroll
        for (int i = 0; i < 16; ++i) qdst[tid + 256 * i] = qsrc[tid + 256 * i];
#pragma unroll
        for (int i = 0; i < 4; ++i) c2s[tid + 256 * i] = g_c2[tid + 256 * i];
    }

    // ---- prologue: x row -> exact L2, stats, int8 pack (xr NOT kept live) ----
    float l2r = 0.f;
    float sx = 0.f, l1x = 0.f;
    int xp[16];
    {
        float xr[DIM];
        const float4* src = (const float4*)(X + (size_t)row * DIM);
#pragma unroll
        for (int q = 0; q < 16; ++q) {
            float4 v = src[q];
            xr[q * 4 + 0] = v.x; xr[q * 4 + 1] = v.y;
            xr[q * 4 + 2] = v.z; xr[q * 4 + 3] = v.w;
        }
#pragma unroll
        for (int d = 0; d < DIM; ++d)
            l2r = __fadd_rn(l2r, __fmul_rn(xr[d], xr[d]));
#pragma unroll
        for (int d = 0; d < DIM; ++d) {
            float a = fabsf(xr[d]);
            sx = fmaxf(sx, a);
            l1x += a;
        }
        sx = fmaxf(sx, 1e-30f);
        const float s127x = 127.f / sx;
#pragma unroll
        for (int i = 0; i < 16; ++i) {
            int p = 0;
#pragma unroll
            for (int b = 0; b < 4; ++b) {
                int q = __float2int_rn(xr[i * 4 + b] * s127x);
                q = max(-127, min(127, q));
                p |= (q & 0xff) << (8 * b);
            }
            xp[i] = p;
        }
    }

    // ---- rigorous filter window (verbatim R13 math, rel_err=0 verified) ----
    int Wint;
    {
        const float sw = g_stat[0], l1wmax = g_stat[1];
        const float invsx = sx * (1.f / 127.f), invsw = sw * (1.f / 127.f);
        const float dxm = 0.6f * invsx + 4e-6f * sx;
        const float dwm = 0.6f * invsw + 4e-6f * sw;
        const float c2max = 64.f * sw * sw;
        const float window = 1.5f * (2.f * (dxm * l1wmax + dwm * (l1x * 1.0001f + 64.f * dxm))
                                     + c2max + 1e-6f);
        const float F2 = 2.f * invsx * invsw;
        Wint = (int)ceilf(window / F2) + 2;
        if (Wint > (1 << 28)) Wint = 1 << 28;
    }

    __syncthreads();   // codebook staged

    float bd = 3.4e38f;
    int   bi = 0;
    int   runmax = -(1 << 29);
    int   thresh = runmax - Wint;     // cached; updated only on candidate hits
    int   cnt = 0;

#define RESCORE(JL) do {                                                     \
        const float* wr_ = W + (size_t)(JL) * DIM;                           \
        const float* xg_ = X + (size_t)row * DIM;                            \
        float cl_ = 0.f;                                                     \
        _Pragma("unroll")                                                    \
        for (int d_ = 0; d_ < DIM; ++d_)                                     \
            cl_ = __fmaf_rn(__ldg(xg_ + d_), __ldg(wr_ + d_), cl_);          \
        float de_ = __fadd_rn(__fsub_rn(l2r, __fmul_rn(2.f, cl_)),           \
                              c2s[JL]);                                      \
        if (de_ < bd) { bd = de_; bi = (JL); }                               \
    } while (0)

    // ---- hot loop: 1024 codes, no syncs; cached-threshold filter ----
    const int* wp = wqs;
#pragma unroll 4
    for (int j = 0; j < KMAX; ++j, wp += 16) {
        const int4* wq4 = (const int4*)wp;             // broadcast LDS
        int4 a0 = wq4[0], a1 = wq4[1], a2 = wq4[2], a3 = wq4[3];
        int da = 0, db = 0, dc = 0, dd = 0;
        da = dp4a(xp[0],  a0.x, da); db = dp4a(xp[1],  a0.y, db);
        dc = dp4a(xp[2],  a0.z, dc); dd = dp4a(xp[3],  a0.w, dd);
        da = dp4a(xp[4],  a1.x, da); db = dp4a(xp[5],  a1.y, db);
        dc = dp4a(xp[6],  a1.z, dc); dd = dp4a(xp[7],  a1.w, dd);
        da = dp4a(xp[8],  a2.x, da); db = dp4a(xp[9],  a2.y, db);
        dc = dp4a(xp[10], a2.z, dc); dd = dp4a(xp[11], a2.w, dd);
        da = dp4a(xp[12], a3.x, da); db = dp4a(xp[13], a3.y, db);
        dc = dp4a(xp[14], a3.z, dc); dd = dp4a(xp[15], a3.w, dd);
        int doti = (da + db) + (dc + dd);
        if (doti >= thresh) {                          // rare
            runmax = max(runmax, doti);
            thresh = runmax - Wint;
            if (cnt == CAP) {                          // flush in order (rarer)
                for (int i = 0; i < cnt; ++i) { int jl = buf[tid * CAP + i]; RESCORE(jl); }
                cnt = 0;
            }
            buf[tid * CAP + cnt] = (unsigned short)j;
            ++cnt;
        }
    }

    // ---- deferred exact rescores (ascending order => first-index ties) ----
    for (int i = 0; i < cnt; ++i) { int jl = buf[tid * CAP + i]; RESCORE(jl); }
#undef RESCORE

    // ---- outputs ----
    if (outI) outI[row] = (float)bi;
    if (outQ) {
        const float4* src = (const float4*)(W + (size_t)bi * DIM);
        float4* dst = (float4*)(outQ + (size_t)row * DIM);
#pragma unroll
        for (int q = 0; q < 16; ++q) dst[q] = __ldg(src + q);
    }
}

// ---------------------------------------------------------------------------
extern "C" void kernel_launch(void* const* d_in, const int* in_sizes, int n_in,
                              void* d_out, int out_size) {
    const float* X = (const float*)d_in[0];
    const float* W = (const float*)d_in[1];
    int N = in_sizes[0] / DIM;
    int K = in_sizes[1] / DIM;

    long long nd = (long long)N * DIM;
    float* outQ = nullptr;
    float* outI = nullptr;
    if ((long long)out_size >= nd + N) { outQ = (float*)d_out; outI = (float*)d_out + nd; }
    else if ((long long)out_size == nd) { outQ = (float*)d_out; }
    else { outI = (float*)d_out; }

    const int smembytes = KMAX * 64 + KMAX * 4 + RPT * CAP * 2;   // 77824 B
    cudaFuncSetAttribute(vq_main, cudaFuncAttributeMaxDynamicSharedMemorySize,
                         smembytes);

    prep_kernel<<<1, 256>>>(W, K);
    vq_main<<<N / RPT, 256, smembytes>>>(X, W, outQ, outI, K);
}